// round 7
// baseline (speedup 1.0000x reference)
#include <cuda_runtime.h>
#include <cfloat>

#define Bn 16
#define Cn 64
#define Nn 2048
#define On 64
#define Kn 20
#define CAP 640
#define CNT_TOT (16*2048*20)

// ---------------- scratch (static device globals; no runtime allocation) ----------------
__device__ float  g_xx[Bn*Nn];               // squared norms
__device__ int    g_cnt[Bn*Nn];              // per-row candidate counts
__device__ int    g_bad[Bn*Nn];              // rows needing repair
__device__ float2 g_cand[(size_t)Bn*Nn*CAP]; // per-row candidate (v, idx) lists (168MB)
__device__ int    g_idx[Bn*Nn*Kn];           // top-K index sets (order arbitrary)
__device__ float  g_U[(size_t)Bn*Nn*On];     // U[b][m][o] = Wd . x  (o contiguous)
__device__ float  g_Bse[(size_t)Bn*Nn*On];   // (V-U)[b][n][o]
__device__ double g_sum[On], g_sumsq[On];
__device__ float  g_scale[On], g_shift[On];

// ---------------- kernel 0a: zero stats accumulators (graph replays!) ----------------
__global__ void k_zero() {
    int o = threadIdx.x;
    g_sum[o] = 0.0; g_sumsq[o] = 0.0;
}
// ---------------- kernel 0b: zero per-row counters / flags ----------------
__global__ void k_zerocnt() {
    int id = blockIdx.x * blockDim.x + threadIdx.x;
    if (id < Bn * Nn) { g_cnt[id] = 0; g_bad[id] = 0; }
}

// ---------------- kernel 1: xx[b,n] = sum_c x^2 ----------------
__global__ void k_xx(const float* __restrict__ x) {
    int id = blockIdx.x * blockDim.x + threadIdx.x;   // 0 .. B*N-1
    if (id >= Bn * Nn) return;
    int b = id / Nn, n = id % Nn;
    const float* xp = x + (size_t)b * Cn * Nn + n;
    float s = 0.f;
#pragma unroll
    for (int c = 0; c < Cn; c++) {
        float v = xp[(size_t)c * Nn];
        s = fmaf(v, v, s);
    }
    g_xx[id] = s;
}

// ---------------- kernel 2: fused neg_dist + threshold candidate append ----------------
// 128x128 tiles, 8x8/thread, triangular grid (tm >= tn). No D matrix is ever
// materialized: elements passing the per-row threshold v >= -xx[row]-40 are
// appended to that row's candidate list. Off-diagonal tiles feed both the
// n-rows (direct) and m-rows (mirror) lists; diagonal tiles compute the full
// square so direct covers everything. Rows whose list under/overflows are
// flagged-by-count and repaired exactly later.
__global__ void __launch_bounds__(256) k_gram(const float* __restrict__ x) {
    __shared__ __align__(16) float sh[64 * 128];   // As|Bs

    int t = blockIdx.x, b = blockIdx.y;
    int tm = (int)((sqrtf(8.f * t + 1.f) - 1.f) * 0.5f);
    while ((tm + 1) * (tm + 2) / 2 <= t) tm++;
    while (tm * (tm + 1) / 2 > t) tm--;
    int tn = t - tm * (tm + 1) / 2;

    int n0 = tn * 128, m0 = tm * 128;
    const float* xb = x + (size_t)b * Cn * Nn;
    int tid = threadIdx.x, tx = tid & 15, ty = tid >> 4;

    float* As = sh;            // [32][128]
    float* Bs = sh + 32 * 128; // [32][128]

    float acc[8][8] = {};

    for (int kc = 0; kc < 64; kc += 32) {
        __syncthreads();
#pragma unroll
        for (int i = 0; i < 4; i++) {
            int f = tid + 256 * i;          // float4 index over 1024
            int c = f >> 5, c4 = (f & 31) * 4;
            *(float4*)&As[c * 128 + c4] = *(const float4*)&xb[(size_t)(kc + c) * Nn + n0 + c4];
            *(float4*)&Bs[c * 128 + c4] = *(const float4*)&xb[(size_t)(kc + c) * Nn + m0 + c4];
        }
        __syncthreads();
#pragma unroll 4
        for (int c = 0; c < 32; c++) {
            float4 a0 = *(float4*)&As[c * 128 + ty * 4];
            float4 a1 = *(float4*)&As[c * 128 + 64 + ty * 4];
            float4 b0 = *(float4*)&Bs[c * 128 + tx * 4];
            float4 b1 = *(float4*)&Bs[c * 128 + 64 + tx * 4];
            float av[8] = {a0.x, a0.y, a0.z, a0.w, a1.x, a1.y, a1.z, a1.w};
            float bv[8] = {b0.x, b0.y, b0.z, b0.w, b1.x, b1.y, b1.z, b1.w};
#pragma unroll
            for (int i = 0; i < 8; i++)
#pragma unroll
                for (int j = 0; j < 8; j++)
                    acc[i][j] = fmaf(av[i], bv[j], acc[i][j]);
        }
    }

    float xn[8], xm[8];
#pragma unroll
    for (int i = 0; i < 4; i++) {
        xn[i]     = g_xx[b * Nn + n0 + ty * 4 + i];
        xn[4 + i] = g_xx[b * Nn + n0 + 64 + ty * 4 + i];
        xm[i]     = g_xx[b * Nn + m0 + tx * 4 + i];
        xm[4 + i] = g_xx[b * Nn + m0 + 64 + tx * 4 + i];
    }

    float vv[8][8];
#pragma unroll
    for (int i = 0; i < 8; i++)
#pragma unroll
        for (int j = 0; j < 8; j++)
            vv[i][j] = 2.f * acc[i][j] - xn[i] - xm[j];

    int rowbase = b * Nn;

    // direct append: row n gets column index m
#pragma unroll
    for (int i = 0; i < 8; i++) {
        int nl = (i < 4) ? (ty * 4 + i) : (64 + ty * 4 + i - 4);
        float thr = -xn[i] - 40.f;
        float hv[8]; int hj[8]; int hits = 0;
#pragma unroll
        for (int j = 0; j < 8; j++) {
            int ml = (j < 4) ? (tx * 4 + j) : (64 + tx * 4 + j - 4);
            if (vv[i][j] >= thr) { hv[hits] = vv[i][j]; hj[hits] = m0 + ml; hits++; }
        }
        if (hits) {
            int pos = atomicAdd(&g_cnt[rowbase + n0 + nl], hits);
            float2* cp = g_cand + (size_t)(rowbase + n0 + nl) * CAP;
            for (int q = 0; q < hits; q++) {
                int p = pos + q;
                if (p < CAP) cp[p] = make_float2(hv[q], __int_as_float(hj[q]));
            }
        }
    }

    // mirror append (off-diagonal tiles): row m gets column index n
    if (tm != tn) {
#pragma unroll
        for (int j = 0; j < 8; j++) {
            int ml = (j < 4) ? (tx * 4 + j) : (64 + tx * 4 + j - 4);
            float thr = -xm[j] - 40.f;
            float hv[8]; int hi_[8]; int hits = 0;
#pragma unroll
            for (int i = 0; i < 8; i++) {
                int nl = (i < 4) ? (ty * 4 + i) : (64 + ty * 4 + i - 4);
                if (vv[i][j] >= thr) { hv[hits] = vv[i][j]; hi_[hits] = n0 + nl; hits++; }
            }
            if (hits) {
                int pos = atomicAdd(&g_cnt[rowbase + m0 + ml], hits);
                float2* cp = g_cand + (size_t)(rowbase + m0 + ml) * CAP;
                for (int q = 0; q < hits; q++) {
                    int p = pos + q;
                    if (p < CAP) cp[p] = make_float2(hv[q], __int_as_float(hi_[q]));
                }
            }
        }
    }
}

// ---------------- kernel 3: select top-K among candidates by exact rank ----------------
// List holds ALL elements with v >= -xx[row]-40; if 20 <= cnt <= CAP the row's
// top-20 is exactly the list's top-20 (rank by value desc, index asc -> same
// set as stable top_k). Otherwise flag for exact repair.
__global__ void __launch_bounds__(256) k_select() {
    int row = blockIdx.x;
    int cnt = g_cnt[row];
    int tid = threadIdx.x;
    if (cnt < Kn || cnt > CAP) {
        if (tid == 0) g_bad[row] = 1;
        return;
    }
    __shared__ unsigned ks[CAP];
    __shared__ int      is[CAP];
    const float2* cp = g_cand + (size_t)row * CAP;
    for (int i = tid; i < cnt; i += 256) {
        float2 c = cp[i];
        unsigned u = __float_as_uint(c.x);
        ks[i] = ((int)u < 0) ? ~u : (u | 0x80000000u);
        is[i] = __float_as_int(c.y);
    }
    __syncthreads();
    int* op = g_idx + row * Kn;
    for (int i = tid; i < cnt; i += 256) {
        unsigned ki = ks[i]; int xi = is[i];
        int r = 0;
        for (int j = 0; j < cnt; j++) {
            unsigned kj = ks[j];
            r += (kj > ki) || (kj == ki && is[j] < xi);
        }
        if (r < Kn) op[r] = xi;
    }
}

// ---------------- kernel 4: exact repair for flagged rows (rare / safety net) ----------
__global__ void __launch_bounds__(256) k_repair(const float* __restrict__ x) {
    int row = blockIdx.x;
    if (!g_bad[row]) return;
    int b = row / Nn, n = row % Nn;
    int tid = threadIdx.x;

    __shared__ float xs[64];
    __shared__ float sv[8];
    __shared__ int   si[8];
    __shared__ int   swin;
    if (tid < 64) xs[tid] = x[(size_t)b * Cn * Nn + (size_t)tid * Nn + n];
    __syncthreads();

    float xxn = g_xx[row];
    const float* xb = x + (size_t)b * Cn * Nn;
    float v[8];
#pragma unroll
    for (int i = 0; i < 8; i++) {
        int m = tid + 256 * i;
        float dot = 0.f;
        for (int c = 0; c < 64; c++) dot = fmaf(xs[c], xb[(size_t)c * Nn + m], dot);
        v[i] = 2.f * dot - xxn - g_xx[b * Nn + m];
    }

    int* op = g_idx + row * Kn;
    for (int k = 0; k < Kn; k++) {
        float bv = -FLT_MAX;
        int   bi = 0x7fffffff;
#pragma unroll
        for (int i = 0; i < 8; i++) {
            int e = tid + (i << 8);
            if (v[i] > bv) { bv = v[i]; bi = e; }
        }
#pragma unroll
        for (int off = 16; off; off >>= 1) {
            float ov = __shfl_down_sync(0xffffffffu, bv, off);
            int   oi = __shfl_down_sync(0xffffffffu, bi, off);
            if (ov > bv || (ov == bv && oi < bi)) { bv = ov; bi = oi; }
        }
        if ((tid & 31) == 0) { sv[tid >> 5] = bv; si[tid >> 5] = bi; }
        __syncthreads();
        if (tid == 0) {
            float fv = sv[0]; int fi = si[0];
#pragma unroll
            for (int w = 1; w < 8; w++)
                if (sv[w] > fv || (sv[w] == fv && si[w] < fi)) { fv = sv[w]; fi = si[w]; }
            swin = fi;
            op[k] = fi;
        }
        __syncthreads();
        int w = swin;
        if ((w & 255) == tid) v[w >> 8] = -FLT_MAX;
    }
}

// ---------------- kernel 5: U = Wd.x , Bse = (Wc-Wd).x  (o-contiguous layout) -----------
__global__ void k_uv(const float* __restrict__ x, const float* __restrict__ W) {
    int b = blockIdx.y;
    int m0 = blockIdx.x * 64;
    __shared__ float Wd[64 * 64];   // [c][o]
    __shared__ float Wf[64 * 64];   // [c][o]  (Wc - Wd)
    __shared__ float xs[64 * 64];   // [c][m]
    int tid = threadIdx.x;
#pragma unroll
    for (int i = 0; i < 16; i++) {
        int id = tid + 256 * i;
        int o = id >> 6, c = id & 63;
        float wd = W[o * 128 + c];
        float wc = W[o * 128 + 64 + c];
        Wd[c * 64 + o] = wd;
        Wf[c * 64 + o] = wc - wd;
        xs[id] = x[(size_t)b * Cn * Nn + (size_t)(id >> 6) * Nn + m0 + (id & 63)];
    }
    __syncthreads();

    int o = tid & 63, mq = tid >> 6;
    float aU[16], aD[16];
#pragma unroll
    for (int t = 0; t < 16; t++) { aU[t] = 0.f; aD[t] = 0.f; }

    for (int c = 0; c < 64; c++) {
        float wu = Wd[c * 64 + o];
        float wf = Wf[c * 64 + o];
#pragma unroll
        for (int t = 0; t < 16; t++) {
            float xv = xs[c * 64 + mq + t * 4];   // broadcast within warp
            aU[t] = fmaf(wu, xv, aU[t]);
            aD[t] = fmaf(wf, xv, aD[t]);
        }
    }
#pragma unroll
    for (int t = 0; t < 16; t++) {
        int m = m0 + mq + t * 4;
        g_U  [((size_t)b * Nn + m) * On + o] = aU[t];
        g_Bse[((size_t)b * Nn + m) * On + o] = aD[t];
    }
}

// ---------------- kernel 6: per-channel sum / sumsq of y over (b,n,k) ----------------
__global__ void k_stats() {
    int b = blockIdx.y;
    int n0 = blockIdx.x * 128;
    int tid = threadIdx.x;
    int o = tid & 63, g = tid >> 6;
    float s = 0.f, s2 = 0.f;
    for (int j = 0; j < 32; j++) {
        int n = n0 + g * 32 + j;
        float bse = g_Bse[((size_t)b * Nn + n) * On + o];
        const int* ip = g_idx + (b * Nn + n) * Kn;
#pragma unroll
        for (int k = 0; k < Kn; k++) {
            int m = ip[k];
            float y = g_U[((size_t)b * Nn + m) * On + o] + bse;
            s += y;
            s2 = fmaf(y, y, s2);
        }
    }
    __shared__ float ss[4][64], ss2[4][64];
    ss[g][o] = s; ss2[g][o] = s2;
    __syncthreads();
    if (g == 0) {
        double ts = (double)ss[0][o] + (double)ss[1][o] + (double)ss[2][o] + (double)ss[3][o];
        double t2 = (double)ss2[0][o] + (double)ss2[1][o] + (double)ss2[2][o] + (double)ss2[3][o];
        atomicAdd(&g_sum[o], ts);
        atomicAdd(&g_sumsq[o], t2);
    }
}

// ---------------- kernel 7: finalize BN affine ----------------
__global__ void k_fin(const float* __restrict__ gamma, const float* __restrict__ beta) {
    int o = threadIdx.x;
    double mean = g_sum[o] / (double)CNT_TOT;
    double var  = g_sumsq[o] / (double)CNT_TOT - mean * mean;
    float sc = gamma[o] * rsqrtf((float)var + 1e-5f);
    g_scale[o] = sc;
    g_shift[o] = beta[o] - (float)mean * sc;
}

// ---------------- kernel 8: normalize + leaky relu + max over k -> out[b][o][n] --------
__global__ void k_out(float* __restrict__ out) {
    int b = blockIdx.y;
    int n0 = blockIdx.x * 32;
    int tid = threadIdx.x;
    int o = tid & 63, nq = tid >> 6;
    __shared__ float sm[64 * 33];
    float sc = g_scale[o], sh = g_shift[o];
    for (int j = 0; j < 8; j++) {
        int nl = nq * 8 + j;
        int n = n0 + nl;
        float bse = g_Bse[((size_t)b * Nn + n) * On + o];
        const int* ip = g_idx + (b * Nn + n) * Kn;
        float mx = -FLT_MAX;
#pragma unroll
        for (int k = 0; k < Kn; k++) {
            int m = ip[k];
            float y  = g_U[((size_t)b * Nn + m) * On + o] + bse;
            float yn = fmaf(y, sc, sh);
            float a  = (yn >= 0.f) ? yn : 0.2f * yn;
            mx = fmaxf(mx, a);
        }
        sm[o * 33 + nl] = mx;
    }
    __syncthreads();
    int nl2 = tid & 31, og = tid >> 5;
#pragma unroll
    for (int j = 0; j < 8; j++) {
        int o2 = og * 8 + j;
        out[((size_t)b * On + o2) * Nn + n0 + nl2] = sm[o2 * 33 + nl2];
    }
}

// ---------------- launch ----------------
extern "C" void kernel_launch(void* const* d_in, const int* in_sizes, int n_in,
                              void* d_out, int out_size) {
    const float* x     = (const float*)d_in[0];
    const float* W     = (const float*)d_in[1];
    const float* gamma = (const float*)d_in[2];
    const float* beta  = (const float*)d_in[3];
    float* out = (float*)d_out;

    k_zero<<<1, 64>>>();
    k_zerocnt<<<(Bn * Nn + 255) / 256, 256>>>();
    k_xx<<<(Bn * Nn) / 256, 256>>>(x);

    dim3 gg(136, 16);                 // triangular tile set, 128x128 tiles
    k_gram<<<gg, 256>>>(x);

    k_select<<<Bn * Nn, 256>>>();
    k_repair<<<Bn * Nn, 256>>>(x);

    dim3 guv(Nn / 64, Bn);
    k_uv<<<guv, 256>>>(x, W);

    dim3 gst(16, Bn);
    k_stats<<<gst, 256>>>();

    k_fin<<<1, 64>>>(gamma, beta);

    dim3 go(Nn / 32, Bn);
    k_out<<<go, 256>>>(out);
}

// round 8
// speedup vs baseline: 1.0525x; 1.0525x over previous
#include <cuda_runtime.h>
#include <cfloat>

#define Bn 16
#define Cn 64
#define Nn 2048
#define On 64
#define Kn 20
#define CAP 640
#define CNT_TOT (16*2048*20)

// ---------------- scratch (static device globals; no runtime allocation) ----------------
__device__ float  g_xx[Bn*Nn];               // squared norms
__device__ int    g_cnt[Bn*Nn];              // per-row candidate counts
__device__ int    g_bad[Bn*Nn];              // rows needing repair
__device__ float2 g_cand[(size_t)Bn*Nn*CAP]; // per-row candidate (v, idx) lists
__device__ int    g_idx[Bn*Nn*Kn];           // top-K index sets (order arbitrary)
__device__ float  g_U[(size_t)Bn*Nn*On];     // U[b][m][o] = Wd . x  (o contiguous)
__device__ float  g_Bse[(size_t)Bn*Nn*On];   // (V-U)[b][n][o]
__device__ double g_sum[On], g_sumsq[On];
__device__ float  g_scale[On], g_shift[On];

// ---------------- kernel 0a: zero stats accumulators (graph replays!) ----------------
__global__ void k_zero() {
    int o = threadIdx.x;
    g_sum[o] = 0.0; g_sumsq[o] = 0.0;
}
// ---------------- kernel 0b: zero per-row counters / flags ----------------
__global__ void k_zerocnt() {
    int id = blockIdx.x * blockDim.x + threadIdx.x;
    if (id < Bn * Nn) { g_cnt[id] = 0; g_bad[id] = 0; }
}

// ---------------- kernel 1: xx[b,n] = sum_c x^2 ----------------
__global__ void k_xx(const float* __restrict__ x) {
    int id = blockIdx.x * blockDim.x + threadIdx.x;   // 0 .. B*N-1
    if (id >= Bn * Nn) return;
    int b = id / Nn, n = id % Nn;
    const float* xp = x + (size_t)b * Cn * Nn + n;
    float s = 0.f;
#pragma unroll
    for (int c = 0; c < Cn; c++) {
        float v = xp[(size_t)c * Nn];
        s = fmaf(v, v, s);
    }
    g_xx[id] = s;
}

// ---------------- kernel 2: fused neg_dist + threshold candidate append ----------------
// 128x128 tiles, 8x8/thread, triangular grid (tm >= tn). Elements passing the
// per-row threshold v >= -xx[row]-40 are appended (per-element immediate
// atomic+store; vv overwrites acc in place to keep registers down). Rows whose
// list under/overflows are repaired exactly later.
__global__ void __launch_bounds__(256) k_gram(const float* __restrict__ x) {
    __shared__ __align__(16) float sh[64 * 128];   // As|Bs

    int t = blockIdx.x, b = blockIdx.y;
    int tm = (int)((sqrtf(8.f * t + 1.f) - 1.f) * 0.5f);
    while ((tm + 1) * (tm + 2) / 2 <= t) tm++;
    while (tm * (tm + 1) / 2 > t) tm--;
    int tn = t - tm * (tm + 1) / 2;

    int n0 = tn * 128, m0 = tm * 128;
    const float* xb = x + (size_t)b * Cn * Nn;
    int tid = threadIdx.x, tx = tid & 15, ty = tid >> 4;

    float* As = sh;            // [32][128]
    float* Bs = sh + 32 * 128; // [32][128]

    float acc[8][8] = {};

    for (int kc = 0; kc < 64; kc += 32) {
        __syncthreads();
#pragma unroll
        for (int i = 0; i < 4; i++) {
            int f = tid + 256 * i;          // float4 index over 1024
            int c = f >> 5, c4 = (f & 31) * 4;
            *(float4*)&As[c * 128 + c4] = *(const float4*)&xb[(size_t)(kc + c) * Nn + n0 + c4];
            *(float4*)&Bs[c * 128 + c4] = *(const float4*)&xb[(size_t)(kc + c) * Nn + m0 + c4];
        }
        __syncthreads();
#pragma unroll 4
        for (int c = 0; c < 32; c++) {
            float4 a0 = *(float4*)&As[c * 128 + ty * 4];
            float4 a1 = *(float4*)&As[c * 128 + 64 + ty * 4];
            float4 b0 = *(float4*)&Bs[c * 128 + tx * 4];
            float4 b1 = *(float4*)&Bs[c * 128 + 64 + tx * 4];
            float av[8] = {a0.x, a0.y, a0.z, a0.w, a1.x, a1.y, a1.z, a1.w};
            float bv[8] = {b0.x, b0.y, b0.z, b0.w, b1.x, b1.y, b1.z, b1.w};
#pragma unroll
            for (int i = 0; i < 8; i++)
#pragma unroll
                for (int j = 0; j < 8; j++)
                    acc[i][j] = fmaf(av[i], bv[j], acc[i][j]);
        }
    }

    float xn[8], xm[8];
#pragma unroll
    for (int i = 0; i < 4; i++) {
        xn[i]     = g_xx[b * Nn + n0 + ty * 4 + i];
        xn[4 + i] = g_xx[b * Nn + n0 + 64 + ty * 4 + i];
        xm[i]     = g_xx[b * Nn + m0 + tx * 4 + i];
        xm[4 + i] = g_xx[b * Nn + m0 + 64 + tx * 4 + i];
    }

    int rowbase = b * Nn;

    // direct append: row n gets column index m (vv folded into acc in place)
#pragma unroll
    for (int i = 0; i < 8; i++) {
        int nl = (i < 4) ? (ty * 4 + i) : (64 + ty * 4 + i - 4);
        int rown = rowbase + n0 + nl;
        float nthr = -xn[i] - 40.f;
        float2* cp = g_cand + (size_t)rown * CAP;
#pragma unroll
        for (int j = 0; j < 8; j++) {
            float v = 2.f * acc[i][j] - xn[i] - xm[j];
            acc[i][j] = v;
            if (v >= nthr) {
                int ml = (j < 4) ? (tx * 4 + j) : (64 + tx * 4 + j - 4);
                int p = atomicAdd(&g_cnt[rown], 1);
                if (p < CAP) cp[p] = make_float2(v, __int_as_float(m0 + ml));
            }
        }
    }

    // mirror append (off-diagonal tiles): row m gets column index n
    if (tm != tn) {
#pragma unroll
        for (int j = 0; j < 8; j++) {
            int ml = (j < 4) ? (tx * 4 + j) : (64 + tx * 4 + j - 4);
            int rowm = rowbase + m0 + ml;
            float mthr = -xm[j] - 40.f;
            float2* cp = g_cand + (size_t)rowm * CAP;
#pragma unroll
            for (int i = 0; i < 8; i++) {
                float v = acc[i][j];
                if (v >= mthr) {
                    int nl = (i < 4) ? (ty * 4 + i) : (64 + ty * 4 + i - 4);
                    int p = atomicAdd(&g_cnt[rowm], 1);
                    if (p < CAP) cp[p] = make_float2(v, __int_as_float(n0 + nl));
                }
            }
        }
    }
}

// ---------------- kernel 3: select top-K among candidates via value histogram ----------
// Candidates hold ALL elements with v >= thr = -xx[row]-40. Bin on the monotone
// map (v - thr) * 255/(-thr) (v in [thr, 0]); elements in bins above the
// threshold bin are emitted directly (only the SET matters downstream); the
// threshold bin gets exact (value desc, idx asc) rank -> identical set to
// stable top_k.
__global__ void __launch_bounds__(256) k_select() {
    int row = blockIdx.x;
    int cnt = g_cnt[row];
    int tid = threadIdx.x;
    if (cnt < Kn || cnt > CAP) {
        if (tid == 0) g_bad[row] = 1;
        return;
    }
    __shared__ float          sv[CAP];
    __shared__ unsigned short si[CAP];
    __shared__ int hist[257];
    __shared__ int s_win, s_kp, s_cnt2;

    float thr = -g_xx[row] - 40.f;
    float scale = 255.f / (-thr);                // thr <= -40 always

    hist[tid] = 0;
    if (tid == 0) { hist[256] = 0; s_cnt2 = 0; }
    __syncthreads();

    const float2* cp = g_cand + (size_t)row * CAP;
    for (int i = tid; i < cnt; i += 256) {
        float2 c = cp[i];
        sv[i] = c.x;
        si[i] = (unsigned short)__float_as_int(c.y);
        int bb = (int)((c.x - thr) * scale);
        bb = bb < 0 ? 0 : (bb > 255 ? 255 : bb);
        atomicAdd(&hist[bb], 1);
    }
    __syncthreads();

    // suffix counts in place: hist[b] = #cands with bin >= b (warp 0 only)
    if (tid < 32) {
        int base = tid * 8, l[8], run = 0;
#pragma unroll
        for (int j = 7; j >= 0; j--) { run += hist[base + j]; l[j] = run; }
        int tot = run, inc = tot;
#pragma unroll
        for (int off = 1; off < 32; off <<= 1) {
            int v = __shfl_down_sync(0xffffffffu, inc, off);
            if (tid + off < 32) inc += v;
        }
        int above = inc - tot;
#pragma unroll
        for (int j = 0; j < 8; j++) hist[base + j] = l[j] + above;
    }
    __syncthreads();
    {
        int cg = hist[tid], cgn = hist[tid + 1];
        if (cg >= Kn && cgn < Kn) { s_win = tid; s_kp = Kn - cgn; }
    }
    __syncthreads();

    int win = s_win, kp = s_kp;
    int* op = g_idx + row * Kn;

    // direct emit of bins above the threshold bin (order arbitrary)
    for (int i = tid; i < cnt; i += 256) {
        int bb = (int)((sv[i] - thr) * scale);
        bb = bb < 0 ? 0 : (bb > 255 ? 255 : bb);
        if (bb > win) op[atomicAdd(&s_cnt2, 1)] = si[i];
    }
    __syncthreads();

    int base = s_cnt2;                            // == Kn - kp
    // exact rank within the threshold bin by (value desc, idx asc)
    for (int i = tid; i < cnt; i += 256) {
        int bb = (int)((sv[i] - thr) * scale);
        bb = bb < 0 ? 0 : (bb > 255 ? 255 : bb);
        if (bb != win) continue;
        float vi = sv[i]; int xi = si[i];
        int r = 0;
        for (int j = 0; j < cnt; j++) {
            int bj = (int)((sv[j] - thr) * scale);
            bj = bj < 0 ? 0 : (bj > 255 ? 255 : bj);
            if (bj != win) continue;
            float vj = sv[j];
            r += (vj > vi) || (vj == vi && si[j] < xi);
        }
        if (r < kp) op[base + r] = xi;
    }
}

// ---------------- kernel 4: exact repair for flagged rows (rare / safety net) ----------
__global__ void __launch_bounds__(256) k_repair(const float* __restrict__ x) {
    int row = blockIdx.x;
    if (!g_bad[row]) return;
    int b = row / Nn, n = row % Nn;
    int tid = threadIdx.x;

    __shared__ float xs[64];
    __shared__ float sv[8];
    __shared__ int   si[8];
    __shared__ int   swin;
    if (tid < 64) xs[tid] = x[(size_t)b * Cn * Nn + (size_t)tid * Nn + n];
    __syncthreads();

    float xxn = g_xx[row];
    const float* xb = x + (size_t)b * Cn * Nn;
    float v[8];
#pragma unroll
    for (int i = 0; i < 8; i++) {
        int m = tid + 256 * i;
        float dot = 0.f;
        for (int c = 0; c < 64; c++) dot = fmaf(xs[c], xb[(size_t)c * Nn + m], dot);
        v[i] = 2.f * dot - xxn - g_xx[b * Nn + m];
    }

    int* op = g_idx + row * Kn;
    for (int k = 0; k < Kn; k++) {
        float bv = -FLT_MAX;
        int   bi = 0x7fffffff;
#pragma unroll
        for (int i = 0; i < 8; i++) {
            int e = tid + (i << 8);
            if (v[i] > bv) { bv = v[i]; bi = e; }
        }
#pragma unroll
        for (int off = 16; off; off >>= 1) {
            float ov = __shfl_down_sync(0xffffffffu, bv, off);
            int   oi = __shfl_down_sync(0xffffffffu, bi, off);
            if (ov > bv || (ov == bv && oi < bi)) { bv = ov; bi = oi; }
        }
        if ((tid & 31) == 0) { sv[tid >> 5] = bv; si[tid >> 5] = bi; }
        __syncthreads();
        if (tid == 0) {
            float fv = sv[0]; int fi = si[0];
#pragma unroll
            for (int w = 1; w < 8; w++)
                if (sv[w] > fv || (sv[w] == fv && si[w] < fi)) { fv = sv[w]; fi = si[w]; }
            swin = fi;
            op[k] = fi;
        }
        __syncthreads();
        int w = swin;
        if ((w & 255) == tid) v[w >> 8] = -FLT_MAX;
    }
}

// ---------------- kernel 5: U = Wd.x , Bse = (Wc-Wd).x  (o-contiguous layout) -----------
__global__ void k_uv(const float* __restrict__ x, const float* __restrict__ W) {
    int b = blockIdx.y;
    int m0 = blockIdx.x * 64;
    __shared__ float Wd[64 * 64];   // [c][o]
    __shared__ float Wf[64 * 64];   // [c][o]  (Wc - Wd)
    __shared__ float xs[64 * 64];   // [c][m]
    int tid = threadIdx.x;
#pragma unroll
    for (int i = 0; i < 16; i++) {
        int id = tid + 256 * i;
        int o = id >> 6, c = id & 63;
        float wd = W[o * 128 + c];
        float wc = W[o * 128 + 64 + c];
        Wd[c * 64 + o] = wd;
        Wf[c * 64 + o] = wc - wd;
        xs[id] = x[(size_t)b * Cn * Nn + (size_t)(id >> 6) * Nn + m0 + (id & 63)];
    }
    __syncthreads();

    int o = tid & 63, mq = tid >> 6;
    float aU[16], aD[16];
#pragma unroll
    for (int t = 0; t < 16; t++) { aU[t] = 0.f; aD[t] = 0.f; }

    for (int c = 0; c < 64; c++) {
        float wu = Wd[c * 64 + o];
        float wf = Wf[c * 64 + o];
#pragma unroll
        for (int t = 0; t < 16; t++) {
            float xv = xs[c * 64 + mq + t * 4];   // broadcast within warp
            aU[t] = fmaf(wu, xv, aU[t]);
            aD[t] = fmaf(wf, xv, aD[t]);
        }
    }
#pragma unroll
    for (int t = 0; t < 16; t++) {
        int m = m0 + mq + t * 4;
        g_U  [((size_t)b * Nn + m) * On + o] = aU[t];
        g_Bse[((size_t)b * Nn + m) * On + o] = aD[t];
    }
}

// ---------------- kernel 6: per-channel sum / sumsq of y over (b,n,k) ----------------
__global__ void k_stats() {
    int b = blockIdx.y;
    int n0 = blockIdx.x * 128;
    int tid = threadIdx.x;
    int o = tid & 63, g = tid >> 6;
    float s = 0.f, s2 = 0.f;
    for (int j = 0; j < 32; j++) {
        int n = n0 + g * 32 + j;
        float bse = g_Bse[((size_t)b * Nn + n) * On + o];
        const int* ip = g_idx + (b * Nn + n) * Kn;
#pragma unroll
        for (int k = 0; k < Kn; k++) {
            int m = ip[k];
            float y = g_U[((size_t)b * Nn + m) * On + o] + bse;
            s += y;
            s2 = fmaf(y, y, s2);
        }
    }
    __shared__ float ss[4][64], ss2[4][64];
    ss[g][o] = s; ss2[g][o] = s2;
    __syncthreads();
    if (g == 0) {
        double ts = (double)ss[0][o] + (double)ss[1][o] + (double)ss[2][o] + (double)ss[3][o];
        double t2 = (double)ss2[0][o] + (double)ss2[1][o] + (double)ss2[2][o] + (double)ss2[3][o];
        atomicAdd(&g_sum[o], ts);
        atomicAdd(&g_sumsq[o], t2);
    }
}

// ---------------- kernel 7: finalize BN affine ----------------
__global__ void k_fin(const float* __restrict__ gamma, const float* __restrict__ beta) {
    int o = threadIdx.x;
    double mean = g_sum[o] / (double)CNT_TOT;
    double var  = g_sumsq[o] / (double)CNT_TOT - mean * mean;
    float sc = gamma[o] * rsqrtf((float)var + 1e-5f);
    g_scale[o] = sc;
    g_shift[o] = beta[o] - (float)mean * sc;
}

// ---------------- kernel 8: normalize + leaky relu + max over k -> out[b][o][n] --------
__global__ void k_out(float* __restrict__ out) {
    int b = blockIdx.y;
    int n0 = blockIdx.x * 32;
    int tid = threadIdx.x;
    int o = tid & 63, nq = tid >> 6;
    __shared__ float sm[64 * 33];
    float sc = g_scale[o], sh = g_shift[o];
    for (int j = 0; j < 8; j++) {
        int nl = nq * 8 + j;
        int n = n0 + nl;
        float bse = g_Bse[((size_t)b * Nn + n) * On + o];
        const int* ip = g_idx + (b * Nn + n) * Kn;
        float mx = -FLT_MAX;
#pragma unroll
        for (int k = 0; k < Kn; k++) {
            int m = ip[k];
            float y  = g_U[((size_t)b * Nn + m) * On + o] + bse;
            float yn = fmaf(y, sc, sh);
            float a  = (yn >= 0.f) ? yn : 0.2f * yn;
            mx = fmaxf(mx, a);
        }
        sm[o * 33 + nl] = mx;
    }
    __syncthreads();
    int nl2 = tid & 31, og = tid >> 5;
#pragma unroll
    for (int j = 0; j < 8; j++) {
        int o2 = og * 8 + j;
        out[((size_t)b * On + o2) * Nn + n0 + nl2] = sm[o2 * 33 + nl2];
    }
}

// ---------------- launch ----------------
extern "C" void kernel_launch(void* const* d_in, const int* in_sizes, int n_in,
                              void* d_out, int out_size) {
    const float* x     = (const float*)d_in[0];
    const float* W     = (const float*)d_in[1];
    const float* gamma = (const float*)d_in[2];
    const float* beta  = (const float*)d_in[3];
    float* out = (float*)d_out;

    k_zero<<<1, 64>>>();
    k_zerocnt<<<(Bn * Nn + 255) / 256, 256>>>();
    k_xx<<<(Bn * Nn) / 256, 256>>>(x);

    dim3 gg(136, 16);                 // triangular tile set, 128x128 tiles
    k_gram<<<gg, 256>>>(x);

    k_select<<<Bn * Nn, 256>>>();
    k_repair<<<Bn * Nn, 256>>>(x);

    dim3 guv(Nn / 64, Bn);
    k_uv<<<guv, 256>>>(x, W);

    dim3 gst(16, Bn);
    k_stats<<<gst, 256>>>();

    k_fin<<<1, 64>>>(gamma, beta);

    dim3 go(Nn / 32, Bn);
    k_out<<<go, 256>>>(out);
}

// round 9
// speedup vs baseline: 2.3050x; 2.1901x over previous
#include <cuda_runtime.h>
#include <cfloat>

#define Bn 16
#define Cn 64
#define Nn 2048
#define On 64
#define Kn 20
#define CNT_TOT (16*2048*20)

// ---------------- scratch (static device globals; no runtime allocation) ----------------
__device__ float  g_D[(size_t)Nn*Nn];        // 16 MB: ONE batch of neg_dist (L2-resident)
__device__ float  g_xx[Bn*Nn];               // squared norms
__device__ int    g_idx[Bn*Nn*Kn];           // top-K index sets (order arbitrary)
__device__ float  g_U[(size_t)Bn*Nn*On];     // U[b][m][o] = Wd . x  (o contiguous)
__device__ float  g_Bse[(size_t)Bn*Nn*On];   // (V-U)[b][n][o]
__device__ double g_sum[On], g_sumsq[On];
__device__ float  g_scale[On], g_shift[On];

// ---------------- kernel 0: zero the stats accumulators (graph replays!) ----------------
__global__ void k_zero() {
    int o = threadIdx.x;
    g_sum[o] = 0.0; g_sumsq[o] = 0.0;
}

// ---------------- kernel 1: xx[b,n] = sum_c x^2 ----------------
__global__ void k_xx(const float* __restrict__ x) {
    int id = blockIdx.x * blockDim.x + threadIdx.x;   // 0 .. B*N-1
    if (id >= Bn * Nn) return;
    int b = id / Nn, n = id % Nn;
    const float* xp = x + (size_t)b * Cn * Nn + n;
    float s = 0.f;
#pragma unroll
    for (int c = 0; c < Cn; c++) {
        float v = xp[(size_t)c * Nn];
        s = fmaf(v, v, s);
    }
    g_xx[id] = s;
}

// ---------------- kernel 2: neg_dist for ONE batch, 128x128 tiles, 8x8/thread ----------
// Triangular tile set (tm >= tn); mirror written via smem transpose. D stays in
// the same 16 MB buffer every batch -> L2-resident for the immediately
// following k_topk launch.
__global__ void __launch_bounds__(256) k_gram(const float* __restrict__ x, int b) {
    __shared__ __align__(16) float sh[64 * 132];   // As|Bs during compute, Ts after

    int t = blockIdx.x;
    int tm = (int)((sqrtf(8.f * t + 1.f) - 1.f) * 0.5f);
    while ((tm + 1) * (tm + 2) / 2 <= t) tm++;
    while (tm * (tm + 1) / 2 > t) tm--;
    int tn = t - tm * (tm + 1) / 2;

    int n0 = tn * 128, m0 = tm * 128;
    const float* xb = x + (size_t)b * Cn * Nn;
    int tid = threadIdx.x, tx = tid & 15, ty = tid >> 4;

    float* As = sh;            // [32][128]
    float* Bs = sh + 32 * 128; // [32][128]

    float acc[8][8] = {};

    for (int kc = 0; kc < 64; kc += 32) {
        __syncthreads();
#pragma unroll
        for (int i = 0; i < 4; i++) {
            int f = tid + 256 * i;          // float4 index over 1024
            int c = f >> 5, c4 = (f & 31) * 4;
            *(float4*)&As[c * 128 + c4] = *(const float4*)&xb[(size_t)(kc + c) * Nn + n0 + c4];
            *(float4*)&Bs[c * 128 + c4] = *(const float4*)&xb[(size_t)(kc + c) * Nn + m0 + c4];
        }
        __syncthreads();
#pragma unroll 4
        for (int c = 0; c < 32; c++) {
            float4 a0 = *(float4*)&As[c * 128 + ty * 4];
            float4 a1 = *(float4*)&As[c * 128 + 64 + ty * 4];
            float4 b0 = *(float4*)&Bs[c * 128 + tx * 4];
            float4 b1 = *(float4*)&Bs[c * 128 + 64 + tx * 4];
            float av[8] = {a0.x, a0.y, a0.z, a0.w, a1.x, a1.y, a1.z, a1.w};
            float bv[8] = {b0.x, b0.y, b0.z, b0.w, b1.x, b1.y, b1.z, b1.w};
#pragma unroll
            for (int i = 0; i < 8; i++)
#pragma unroll
                for (int j = 0; j < 8; j++)
                    acc[i][j] = fmaf(av[i], bv[j], acc[i][j]);
        }
    }

    float xn[8], xm[8];
#pragma unroll
    for (int i = 0; i < 4; i++) {
        xn[i]     = g_xx[b * Nn + n0 + ty * 4 + i];
        xn[4 + i] = g_xx[b * Nn + n0 + 64 + ty * 4 + i];
        xm[i]     = g_xx[b * Nn + m0 + tx * 4 + i];
        xm[4 + i] = g_xx[b * Nn + m0 + 64 + tx * 4 + i];
    }

    float vv[8][8];
#pragma unroll
    for (int i = 0; i < 8; i++)
#pragma unroll
        for (int j = 0; j < 8; j++)
            vv[i][j] = 2.f * acc[i][j] - xn[i] - xm[j];

    float* Db = g_D;

    // direct store: D[n][m]
#pragma unroll
    for (int i = 0; i < 8; i++) {
        int nl = (i < 4) ? (ty * 4 + i) : (64 + ty * 4 + i - 4);
        *(float4*)&Db[(size_t)(n0 + nl) * Nn + m0 + tx * 4] =
            make_float4(vv[i][0], vv[i][1], vv[i][2], vv[i][3]);
        *(float4*)&Db[(size_t)(n0 + nl) * Nn + m0 + 64 + tx * 4] =
            make_float4(vv[i][4], vv[i][5], vv[i][6], vv[i][7]);
    }

    // mirror store: D[m][n] via smem transpose (two 64-col halves)
    if (tm != tn) {
        float* Ts = sh;                       // [64][132]
#pragma unroll
        for (int h = 0; h < 2; h++) {
            __syncthreads();
#pragma unroll
            for (int i = 0; i < 8; i++) {
                int nl = (i < 4) ? (ty * 4 + i) : (64 + ty * 4 + i - 4);
#pragma unroll
                for (int j = 0; j < 4; j++)
                    Ts[(tx * 4 + j) * 132 + nl] = vv[i][h * 4 + j];
            }
            __syncthreads();
#pragma unroll
            for (int q = 0; q < 8; q++) {
                int f = tid + 256 * q;        // over 64*32 float4
                int mc = f >> 5, n4 = (f & 31) * 4;
                float4 w = *(float4*)&Ts[mc * 132 + n4];
                *(float4*)&Db[(size_t)(m0 + h * 64 + mc) * Nn + n0 + n4] = w;
            }
        }
    }
}

// ---------------- kernel 3: top-K=20 per row via value-scaled 256-bin histogram --------
// Reads the L2-resident batch D. Bin on (v - rowmin) * 255/(rowmax - rowmin).
// Only the SET of top-K indices matters downstream; threshold-bin ties resolved
// by exact (key desc, idx asc) rank -> identical set to stable top_k.
__global__ void __launch_bounds__(256) k_topk(int b) {
    int n = blockIdx.x;                         // row within batch
    int row = b * Nn + n;
    const float4* d4 = (const float4*)(g_D + (size_t)n * Nn);
    int tid = threadIdx.x;                      // 256 threads, 8 elems each
    int lane = tid & 31, warp = tid >> 5;

    __shared__ float s_wmax[8], s_wmin[8];
    __shared__ float s_M, s_m;
    __shared__ int   hist[257];                 // suffix-scanned in place
    __shared__ int   s_win, s_kp, s_cnt, s_cc;
    __shared__ unsigned       ck[2048];         // threshold-bin candidates
    __shared__ unsigned short ci[2048];

    float4 a = d4[tid * 2], b4 = d4[tid * 2 + 1];
    float f[8] = {a.x, a.y, a.z, a.w, b4.x, b4.y, b4.z, b4.w};

    // row max / min (registers + shfl only)
    float mx = f[0], mn = f[0];
#pragma unroll
    for (int i = 1; i < 8; i++) { mx = fmaxf(mx, f[i]); mn = fminf(mn, f[i]); }
#pragma unroll
    for (int off = 16; off; off >>= 1) {
        mx = fmaxf(mx, __shfl_xor_sync(0xffffffffu, mx, off));
        mn = fminf(mn, __shfl_xor_sync(0xffffffffu, mn, off));
    }
    if (lane == 0) { s_wmax[warp] = mx; s_wmin[warp] = mn; }
    hist[tid] = 0;
    if (tid == 0) { hist[256] = 0; s_cnt = 0; s_cc = 0; }
    __syncthreads();
    if (tid == 0) {
        float M = s_wmax[0], m = s_wmin[0];
#pragma unroll
        for (int w = 1; w < 8; w++) { M = fmaxf(M, s_wmax[w]); m = fminf(m, s_wmin[w]); }
        s_M = M; s_m = m;
    }
    __syncthreads();

    float m = s_m, range = s_M - s_m;
    float sc = (range > 0.f) ? (255.f / range) : 0.f;

    int bin[8];
#pragma unroll
    for (int i = 0; i < 8; i++) {
        int bb = (int)((f[i] - m) * sc);
        bin[i] = bb > 255 ? 255 : bb;
        atomicAdd(&hist[bin[i]], 1);
    }
    __syncthreads();

    // suffix counts in place: hist[b] = #elems with bin >= b (warp 0 only)
    if (tid < 32) {
        int base = tid * 8, l[8], run = 0;
#pragma unroll
        for (int j = 7; j >= 0; j--) { run += hist[base + j]; l[j] = run; }
        int tot = run, inc = tot;
#pragma unroll
        for (int off = 1; off < 32; off <<= 1) {
            int v = __shfl_down_sync(0xffffffffu, inc, off);
            if (tid + off < 32) inc += v;
        }
        int above = inc - tot;
#pragma unroll
        for (int j = 0; j < 8; j++) hist[base + j] = l[j] + above;
    }
    __syncthreads();
    {
        int cg = hist[tid], cgn = hist[tid + 1];
        if (cg >= Kn && cgn < Kn) { s_win = tid; s_kp = Kn - cgn; }
    }
    __syncthreads();

    int win = s_win;
    int* op = g_idx + row * Kn;

    // plain predicated emit: >win hits ~20/2048, ==win ~dozens -> atomics are cheap
#pragma unroll
    for (int i = 0; i < 8; i++) {
        int e = tid * 8 + i;
        if (bin[i] > win) {
            op[atomicAdd(&s_cnt, 1)] = e;        // definitely in top-K (order arbitrary)
        } else if (bin[i] == win) {
            unsigned u = __float_as_uint(f[i]);
            unsigned key = ((int)u < 0) ? ~u : (u | 0x80000000u);
            int p = atomicAdd(&s_cc, 1);
            ck[p] = key; ci[p] = (unsigned short)e;
        }
    }
    __syncthreads();

    int cc = s_cc, kp = s_kp, base = s_cnt;      // base == Kn - kp
    // exact rank among threshold-bin candidates by (key desc, idx asc)
    for (int i = tid; i < cc; i += 256) {
        unsigned kk = ck[i]; unsigned short xi = ci[i];
        int r = 0;
        for (int j = 0; j < cc; j++) {
            unsigned kj = ck[j];
            r += (kj > kk) || (kj == kk && ci[j] < xi);
        }
        if (r < kp) op[base + r] = xi;
    }
}

// ---------------- kernel 4: U = Wd.x , Bse = (Wc-Wd).x  (o-contiguous layout) -----------
__global__ void k_uv(const float* __restrict__ x, const float* __restrict__ W) {
    int b = blockIdx.y;
    int m0 = blockIdx.x * 64;
    __shared__ float Wd[64 * 64];   // [c][o]
    __shared__ float Wf[64 * 64];   // [c][o]  (Wc - Wd)
    __shared__ float xs[64 * 64];   // [c][m]
    int tid = threadIdx.x;
#pragma unroll
    for (int i = 0; i < 16; i++) {
        int id = tid + 256 * i;
        int o = id >> 6, c = id & 63;
        float wd = W[o * 128 + c];
        float wc = W[o * 128 + 64 + c];
        Wd[c * 64 + o] = wd;
        Wf[c * 64 + o] = wc - wd;
        xs[id] = x[(size_t)b * Cn * Nn + (size_t)(id >> 6) * Nn + m0 + (id & 63)];
    }
    __syncthreads();

    int o = tid & 63, mq = tid >> 6;
    float aU[16], aD[16];
#pragma unroll
    for (int t = 0; t < 16; t++) { aU[t] = 0.f; aD[t] = 0.f; }

    for (int c = 0; c < 64; c++) {
        float wu = Wd[c * 64 + o];
        float wf = Wf[c * 64 + o];
#pragma unroll
        for (int t = 0; t < 16; t++) {
            float xv = xs[c * 64 + mq + t * 4];   // broadcast within warp
            aU[t] = fmaf(wu, xv, aU[t]);
            aD[t] = fmaf(wf, xv, aD[t]);
        }
    }
#pragma unroll
    for (int t = 0; t < 16; t++) {
        int m = m0 + mq + t * 4;
        g_U  [((size_t)b * Nn + m) * On + o] = aU[t];
        g_Bse[((size_t)b * Nn + m) * On + o] = aD[t];
    }
}

// ---------------- kernel 5: per-channel sum / sumsq of y over (b,n,k) ----------------
__global__ void k_stats() {
    int b = blockIdx.y;
    int n0 = blockIdx.x * 128;
    int tid = threadIdx.x;
    int o = tid & 63, g = tid >> 6;
    float s = 0.f, s2 = 0.f;
    for (int j = 0; j < 32; j++) {
        int n = n0 + g * 32 + j;
        float bse = g_Bse[((size_t)b * Nn + n) * On + o];
        const int* ip = g_idx + (b * Nn + n) * Kn;
#pragma unroll
        for (int k = 0; k < Kn; k++) {
            int m = ip[k];
            float y = g_U[((size_t)b * Nn + m) * On + o] + bse;
            s += y;
            s2 = fmaf(y, y, s2);
        }
    }
    __shared__ float ss[4][64], ss2[4][64];
    ss[g][o] = s; ss2[g][o] = s2;
    __syncthreads();
    if (g == 0) {
        double ts = (double)ss[0][o] + (double)ss[1][o] + (double)ss[2][o] + (double)ss[3][o];
        double t2 = (double)ss2[0][o] + (double)ss2[1][o] + (double)ss2[2][o] + (double)ss2[3][o];
        atomicAdd(&g_sum[o], ts);
        atomicAdd(&g_sumsq[o], t2);
    }
}

// ---------------- kernel 6: finalize BN affine ----------------
__global__ void k_fin(const float* __restrict__ gamma, const float* __restrict__ beta) {
    int o = threadIdx.x;
    double mean = g_sum[o] / (double)CNT_TOT;
    double var  = g_sumsq[o] / (double)CNT_TOT - mean * mean;
    float sc = gamma[o] * rsqrtf((float)var + 1e-5f);
    g_scale[o] = sc;
    g_shift[o] = beta[o] - (float)mean * sc;
}

// ---------------- kernel 7: normalize + leaky relu + max over k -> out[b][o][n] --------
__global__ void k_out(float* __restrict__ out) {
    int b = blockIdx.y;
    int n0 = blockIdx.x * 32;
    int tid = threadIdx.x;
    int o = tid & 63, nq = tid >> 6;
    __shared__ float sm[64 * 33];
    float sc = g_scale[o], sh = g_shift[o];
    for (int j = 0; j < 8; j++) {
        int nl = nq * 8 + j;
        int n = n0 + nl;
        float bse = g_Bse[((size_t)b * Nn + n) * On + o];
        const int* ip = g_idx + (b * Nn + n) * Kn;
        float mx = -FLT_MAX;
#pragma unroll
        for (int k = 0; k < Kn; k++) {
            int m = ip[k];
            float y  = g_U[((size_t)b * Nn + m) * On + o] + bse;
            float yn = fmaf(y, sc, sh);
            float a  = (yn >= 0.f) ? yn : 0.2f * yn;
            mx = fmaxf(mx, a);
        }
        sm[o * 33 + nl] = mx;
    }
    __syncthreads();
    int nl2 = tid & 31, og = tid >> 5;
#pragma unroll
    for (int j = 0; j < 8; j++) {
        int o2 = og * 8 + j;
        out[((size_t)b * On + o2) * Nn + n0 + nl2] = sm[o2 * 33 + nl2];
    }
}

// ---------------- launch ----------------
extern "C" void kernel_launch(void* const* d_in, const int* in_sizes, int n_in,
                              void* d_out, int out_size) {
    const float* x     = (const float*)d_in[0];
    const float* W     = (const float*)d_in[1];
    const float* gamma = (const float*)d_in[2];
    const float* beta  = (const float*)d_in[3];
    float* out = (float*)d_out;

    k_zero<<<1, 64>>>();
    k_xx<<<(Bn * Nn) / 256, 256>>>(x);

    // per-batch gram -> topk so the 16 MB D buffer stays L2-resident
    for (int b = 0; b < Bn; b++) {
        k_gram<<<136, 256>>>(x, b);
        k_topk<<<Nn, 256>>>(b);
    }

    dim3 guv(Nn / 64, Bn);
    k_uv<<<guv, 256>>>(x, W);

    dim3 gst(16, Bn);
    k_stats<<<gst, 256>>>();

    k_fin<<<1, 64>>>(gamma, beta);

    dim3 go(Nn / 32, Bn);
    k_out<<<go, 256>>>(out);
}

// round 10
// speedup vs baseline: 2.5694x; 1.1147x over previous
#include <cuda_runtime.h>
#include <cfloat>

#define Bn 16
#define Cn 64
#define Nn 2048
#define On 64
#define Kn 20
#define CNT_TOT (16*2048*20)

// ---------------- scratch (static device globals; no runtime allocation) ----------------
__device__ float  g_D[(size_t)Bn*Nn*Nn];     // 256 MB neg_dist scratch
__device__ float  g_xx[Bn*Nn];               // squared norms
__device__ int    g_idx[Bn*Nn*Kn];           // top-K index sets (order arbitrary)
__device__ float  g_U[(size_t)Bn*Nn*On];     // U[b][m][o] = Wd . x  (o contiguous)
__device__ float  g_Bse[(size_t)Bn*Nn*On];   // (V-U)[b][n][o]
__device__ double g_sum[On], g_sumsq[On];
__device__ float  g_scale[On], g_shift[On];

// ---------------- kernel 0: zero the stats accumulators (graph replays!) ----------------
__global__ void k_zero() {
    int o = threadIdx.x;
    g_sum[o] = 0.0; g_sumsq[o] = 0.0;
}

// ---------------- kernel 1: xx[b,n] = sum_c x^2 ----------------
__global__ void k_xx(const float* __restrict__ x) {
    int id = blockIdx.x * blockDim.x + threadIdx.x;   // 0 .. B*N-1
    if (id >= Bn * Nn) return;
    int b = id / Nn, n = id % Nn;
    const float* xp = x + (size_t)b * Cn * Nn + n;
    float s = 0.f;
#pragma unroll
    for (int c = 0; c < Cn; c++) {
        float v = xp[(size_t)c * Nn];
        s = fmaf(v, v, s);
    }
    g_xx[id] = s;
}

// ---------------- kernel 2: neg_dist 128x128 tiles, 8x8 per thread ----------------
// Triangular grid (tm >= tn); mirror written via smem transpose.
__global__ void __launch_bounds__(256) k_gram(const float* __restrict__ x) {
    __shared__ __align__(16) float sh[64 * 132];   // As|Bs during compute, Ts after

    int t = blockIdx.x, b = blockIdx.y;
    int tm = (int)((sqrtf(8.f * t + 1.f) - 1.f) * 0.5f);
    while ((tm + 1) * (tm + 2) / 2 <= t) tm++;
    while (tm * (tm + 1) / 2 > t) tm--;
    int tn = t - tm * (tm + 1) / 2;

    int n0 = tn * 128, m0 = tm * 128;
    const float* xb = x + (size_t)b * Cn * Nn;
    int tid = threadIdx.x, tx = tid & 15, ty = tid >> 4;

    float* As = sh;            // [32][128]
    float* Bs = sh + 32 * 128; // [32][128]

    float acc[8][8] = {};

    for (int kc = 0; kc < 64; kc += 32) {
        __syncthreads();
#pragma unroll
        for (int i = 0; i < 4; i++) {
            int f = tid + 256 * i;          // float4 index over 1024
            int c = f >> 5, c4 = (f & 31) * 4;
            *(float4*)&As[c * 128 + c4] = *(const float4*)&xb[(size_t)(kc + c) * Nn + n0 + c4];
            *(float4*)&Bs[c * 128 + c4] = *(const float4*)&xb[(size_t)(kc + c) * Nn + m0 + c4];
        }
        __syncthreads();
#pragma unroll 4
        for (int c = 0; c < 32; c++) {
            float4 a0 = *(float4*)&As[c * 128 + ty * 4];
            float4 a1 = *(float4*)&As[c * 128 + 64 + ty * 4];
            float4 b0 = *(float4*)&Bs[c * 128 + tx * 4];
            float4 b1 = *(float4*)&Bs[c * 128 + 64 + tx * 4];
            float av[8] = {a0.x, a0.y, a0.z, a0.w, a1.x, a1.y, a1.z, a1.w};
            float bv[8] = {b0.x, b0.y, b0.z, b0.w, b1.x, b1.y, b1.z, b1.w};
#pragma unroll
            for (int i = 0; i < 8; i++)
#pragma unroll
                for (int j = 0; j < 8; j++)
                    acc[i][j] = fmaf(av[i], bv[j], acc[i][j]);
        }
    }

    float xn[8], xm[8];
#pragma unroll
    for (int i = 0; i < 4; i++) {
        xn[i]     = g_xx[b * Nn + n0 + ty * 4 + i];
        xn[4 + i] = g_xx[b * Nn + n0 + 64 + ty * 4 + i];
        xm[i]     = g_xx[b * Nn + m0 + tx * 4 + i];
        xm[4 + i] = g_xx[b * Nn + m0 + 64 + tx * 4 + i];
    }

    float vv[8][8];
#pragma unroll
    for (int i = 0; i < 8; i++)
#pragma unroll
        for (int j = 0; j < 8; j++)
            vv[i][j] = 2.f * acc[i][j] - xn[i] - xm[j];

    float* Db = g_D + (size_t)b * Nn * Nn;

    // direct store: D[n][m]
#pragma unroll
    for (int i = 0; i < 8; i++) {
        int nl = (i < 4) ? (ty * 4 + i) : (64 + ty * 4 + i - 4);
        *(float4*)&Db[(size_t)(n0 + nl) * Nn + m0 + tx * 4] =
            make_float4(vv[i][0], vv[i][1], vv[i][2], vv[i][3]);
        *(float4*)&Db[(size_t)(n0 + nl) * Nn + m0 + 64 + tx * 4] =
            make_float4(vv[i][4], vv[i][5], vv[i][6], vv[i][7]);
    }

    // mirror store: D[m][n] via smem transpose (two 64-col halves)
    if (tm != tn) {
        float* Ts = sh;                       // [64][132]
#pragma unroll
        for (int h = 0; h < 2; h++) {
            __syncthreads();
#pragma unroll
            for (int i = 0; i < 8; i++) {
                int nl = (i < 4) ? (ty * 4 + i) : (64 + ty * 4 + i - 4);
#pragma unroll
                for (int j = 0; j < 4; j++)
                    Ts[(tx * 4 + j) * 132 + nl] = vv[i][h * 4 + j];
            }
            __syncthreads();
#pragma unroll
            for (int q = 0; q < 8; q++) {
                int f = tid + 256 * q;        // over 64*32 float4
                int mc = f >> 5, n4 = (f & 31) * 4;
                float4 w = *(float4*)&Ts[mc * 132 + n4];
                *(float4*)&Db[(size_t)(m0 + h * 64 + mc) * Nn + n0 + n4] = w;
            }
        }
    }
}

// ---------------- kernel 3: top-K=20 per row via barrier-count binary search ----------
// Row max is exactly 0 (self-distance; bit-identical FMA order vs k_xx), values
// <= ~0. Binary-search a value threshold with a block-wide count (register
// compares + __reduce_add_sync + 1 barrier/iter, ping-pong counters) until
// #elems >= lo is in [20, 64]; exact (value desc, idx asc) rank among those
// candidates -> identical set to stable top_k. Tie-collapse falls back to
// exact iterative argmax. Only the SET matters downstream.
__global__ void __launch_bounds__(256) k_topk() {
    int row = blockIdx.x;                       // b*N + n
    const float4* d4 = (const float4*)(g_D + (size_t)row * Nn);
    int tid = threadIdx.x;                      // 256 threads, 8 elems each
    int lane = tid & 31;

    __shared__ int s_c[2];
    __shared__ int s_cc;
    __shared__ float          cv[320];
    __shared__ unsigned short cix[320];
    __shared__ float sv[8];
    __shared__ int   si[8];
    __shared__ int   swin;

    float4 a = d4[tid * 2], b4 = d4[tid * 2 + 1];
    float f[8] = {a.x, a.y, a.z, a.w, b4.x, b4.y, b4.z, b4.w};

    if (tid < 2) s_c[tid] = 0;
    if (tid == 0) s_cc = 0;
    __syncthreads();

    float lo = -40.f, hi = 1.0f;
    int cnt_lo = 0;
    int p = 0;

    // bracket expansion: guarantee count(>= lo) >= K
    for (int it = 0; it < 14; it++) {
        int c = 0;
#pragma unroll
        for (int i = 0; i < 8; i++) c += (f[i] >= lo);
        c = __reduce_add_sync(0xffffffffu, c);
        if (lane == 0 && c) atomicAdd(&s_c[p], c);
        if (tid == 0) s_c[p ^ 1] = 0;
        __syncthreads();
        cnt_lo = s_c[p];
        p ^= 1;
        if (cnt_lo >= Kn) break;
        hi = lo; lo *= 2.f;
    }

    // binary search: shrink until count(>= lo) <= 64 (invariant: >= K)
    for (int it = 0; it < 40 && cnt_lo > 64; it++) {
        float mid = 0.5f * (lo + hi);
        if (mid <= lo || mid >= hi) break;      // interval collapsed (mass ties)
        int c = 0;
#pragma unroll
        for (int i = 0; i < 8; i++) c += (f[i] >= mid);
        c = __reduce_add_sync(0xffffffffu, c);
        if (lane == 0 && c) atomicAdd(&s_c[p], c);
        if (tid == 0) s_c[p ^ 1] = 0;
        __syncthreads();
        int cm = s_c[p];
        p ^= 1;
        if (cm >= Kn) { lo = mid; cnt_lo = cm; } else hi = mid;
    }

    int* op = g_idx + row * Kn;

    if (cnt_lo <= 320) {
        // collect candidates and rank exactly by (value desc, idx asc)
#pragma unroll
        for (int i = 0; i < 8; i++) {
            if (f[i] >= lo) {
                int q = atomicAdd(&s_cc, 1);
                cv[q] = f[i]; cix[q] = (unsigned short)(tid * 8 + i);
            }
        }
        __syncthreads();
        int cc = s_cc;                           // == cnt_lo
        for (int i = tid; i < cc; i += 256) {
            float vi = cv[i]; int xi = cix[i];
            int r = 0;
            for (int j = 0; j < cc; j++) {
                float vj = cv[j];
                r += (vj > vi) || (vj == vi && cix[j] < xi);
            }
            if (r < Kn) op[r] = xi;
        }
        return;                                  // uniform: cnt_lo is block-uniform
    }

    // pathological fallback (mass exact ties): exact iterative argmax
    for (int k = 0; k < Kn; k++) {
        float bv = -FLT_MAX;
        int   bi = 0x7fffffff;
#pragma unroll
        for (int i = 0; i < 8; i++) {
            int e = tid + (i << 8);
            if (f[i] > bv) { bv = f[i]; bi = e; }
        }
#pragma unroll
        for (int off = 16; off; off >>= 1) {
            float ov = __shfl_down_sync(0xffffffffu, bv, off);
            int   oi = __shfl_down_sync(0xffffffffu, bi, off);
            if (ov > bv || (ov == bv && oi < bi)) { bv = ov; bi = oi; }
        }
        if ((tid & 31) == 0) { sv[tid >> 5] = bv; si[tid >> 5] = bi; }
        __syncthreads();
        if (tid == 0) {
            float fv = sv[0]; int fi = si[0];
#pragma unroll
            for (int w = 1; w < 8; w++)
                if (sv[w] > fv || (sv[w] == fv && si[w] < fi)) { fv = sv[w]; fi = si[w]; }
            swin = fi;
            op[k] = fi;
        }
        __syncthreads();
        int w = swin;
        if ((w & 255) == tid) f[w >> 8] = -FLT_MAX;
    }
}

// ---------------- kernel 4: U = Wd.x , Bse = (Wc-Wd).x  (o-contiguous layout) -----------
__global__ void k_uv(const float* __restrict__ x, const float* __restrict__ W) {
    int b = blockIdx.y;
    int m0 = blockIdx.x * 64;
    __shared__ float Wd[64 * 64];   // [c][o]
    __shared__ float Wf[64 * 64];   // [c][o]  (Wc - Wd)
    __shared__ float xs[64 * 64];   // [c][m]
    int tid = threadIdx.x;
#pragma unroll
    for (int i = 0; i < 16; i++) {
        int id = tid + 256 * i;
        int o = id >> 6, c = id & 63;
        float wd = W[o * 128 + c];
        float wc = W[o * 128 + 64 + c];
        Wd[c * 64 + o] = wd;
        Wf[c * 64 + o] = wc - wd;
        xs[id] = x[(size_t)b * Cn * Nn + (size_t)(id >> 6) * Nn + m0 + (id & 63)];
    }
    __syncthreads();

    int o = tid & 63, mq = tid >> 6;
    float aU[16], aD[16];
#pragma unroll
    for (int t = 0; t < 16; t++) { aU[t] = 0.f; aD[t] = 0.f; }

    for (int c = 0; c < 64; c++) {
        float wu = Wd[c * 64 + o];
        float wf = Wf[c * 64 + o];
#pragma unroll
        for (int t = 0; t < 16; t++) {
            float xv = xs[c * 64 + mq + t * 4];   // broadcast within warp
            aU[t] = fmaf(wu, xv, aU[t]);
            aD[t] = fmaf(wf, xv, aD[t]);
        }
    }
#pragma unroll
    for (int t = 0; t < 16; t++) {
        int m = m0 + mq + t * 4;
        g_U  [((size_t)b * Nn + m) * On + o] = aU[t];
        g_Bse[((size_t)b * Nn + m) * On + o] = aD[t];
    }
}

// ---------------- kernel 5: per-channel sum / sumsq of y over (b,n,k) ----------------
__global__ void k_stats() {
    int b = blockIdx.y;
    int n0 = blockIdx.x * 128;
    int tid = threadIdx.x;
    int o = tid & 63, g = tid >> 6;
    float s = 0.f, s2 = 0.f;
    for (int j = 0; j < 32; j++) {
        int n = n0 + g * 32 + j;
        float bse = g_Bse[((size_t)b * Nn + n) * On + o];
        const int* ip = g_idx + (b * Nn + n) * Kn;
#pragma unroll
        for (int k = 0; k < Kn; k++) {
            int m = ip[k];
            float y = g_U[((size_t)b * Nn + m) * On + o] + bse;
            s += y;
            s2 = fmaf(y, y, s2);
        }
    }
    __shared__ float ss[4][64], ss2[4][64];
    ss[g][o] = s; ss2[g][o] = s2;
    __syncthreads();
    if (g == 0) {
        double ts = (double)ss[0][o] + (double)ss[1][o] + (double)ss[2][o] + (double)ss[3][o];
        double t2 = (double)ss2[0][o] + (double)ss2[1][o] + (double)ss2[2][o] + (double)ss2[3][o];
        atomicAdd(&g_sum[o], ts);
        atomicAdd(&g_sumsq[o], t2);
    }
}

// ---------------- kernel 6: finalize BN affine ----------------
__global__ void k_fin(const float* __restrict__ gamma, const float* __restrict__ beta) {
    int o = threadIdx.x;
    double mean = g_sum[o] / (double)CNT_TOT;
    double var  = g_sumsq[o] / (double)CNT_TOT - mean * mean;
    float sc = gamma[o] * rsqrtf((float)var + 1e-5f);
    g_scale[o] = sc;
    g_shift[o] = beta[o] - (float)mean * sc;
}

// ---------------- kernel 7: normalize + leaky relu + max over k -> out[b][o][n] --------
__global__ void k_out(float* __restrict__ out) {
    int b = blockIdx.y;
    int n0 = blockIdx.x * 32;
    int tid = threadIdx.x;
    int o = tid & 63, nq = tid >> 6;
    __shared__ float sm[64 * 33];
    float sc = g_scale[o], sh = g_shift[o];
    for (int j = 0; j < 8; j++) {
        int nl = nq * 8 + j;
        int n = n0 + nl;
        float bse = g_Bse[((size_t)b * Nn + n) * On + o];
        const int* ip = g_idx + (b * Nn + n) * Kn;
        float mx = -FLT_MAX;
#pragma unroll
        for (int k = 0; k < Kn; k++) {
            int m = ip[k];
            float y  = g_U[((size_t)b * Nn + m) * On + o] + bse;
            float yn = fmaf(y, sc, sh);
            float a  = (yn >= 0.f) ? yn : 0.2f * yn;
            mx = fmaxf(mx, a);
        }
        sm[o * 33 + nl] = mx;
    }
    __syncthreads();
    int nl2 = tid & 31, og = tid >> 5;
#pragma unroll
    for (int j = 0; j < 8; j++) {
        int o2 = og * 8 + j;
        out[((size_t)b * On + o2) * Nn + n0 + nl2] = sm[o2 * 33 + nl2];
    }
}

// ---------------- launch ----------------
extern "C" void kernel_launch(void* const* d_in, const int* in_sizes, int n_in,
                              void* d_out, int out_size) {
    const float* x     = (const float*)d_in[0];
    const float* W     = (const float*)d_in[1];
    const float* gamma = (const float*)d_in[2];
    const float* beta  = (const float*)d_in[3];
    float* out = (float*)d_out;

    k_zero<<<1, 64>>>();
    k_xx<<<(Bn * Nn) / 256, 256>>>(x);

    dim3 gg(136, 16);                 // triangular tile set, 128x128 tiles
    k_gram<<<gg, 256>>>(x);

    k_topk<<<Bn * Nn, 256>>>();

    dim3 guv(Nn / 64, Bn);
    k_uv<<<guv, 256>>>(x, W);

    dim3 gst(16, Bn);
    k_stats<<<gst, 256>>>();

    k_fin<<<1, 64>>>(gamma, beta);

    dim3 go(Nn / 32, Bn);
    k_out<<<go, 256>>>(out);
}